// round 4
// baseline (speedup 1.0000x reference)
#include <cuda_runtime.h>
#include <cuda_bf16.h>

#define N_VERTS 262144
#define N_PAIRS 8388608
#define NW      52429        // ceil(N_VERTS/5) packed words, 6 bits/vertex
#define NWPAD   52432        // padded to /4 for int4 staging
#define DHAT2   0.0025f
#define EPSF    1e-12f
// Conservative filter threshold in CELL units (cell = 0.125):
// e_pt <= sqrt(2)*(0.0625 + 0.005) = 0.09546 ; r = 0.05 + 2e = 0.2409
// (r/0.125)^2 = 3.715  -> 3.75 with margin
#define R2CELL  3.75f

__device__ float2   g_coords[N_VERTS];   // 2 MB, L2-resident
__device__ unsigned g_qtab[NWPAD];       // 6-bit quantized coords, 5/word

// ---------------------------------------------------------------- setup
// One thread per packed word: build coords for 5 verts, quantize, pack.
__global__ void setup_kernel(const float* __restrict__ Uu,
                             const float* __restrict__ rest,
                             float* __restrict__ out) {
    int w = blockIdx.x * blockDim.x + threadIdx.x;
    if (w >= NWPAD) return;
    const float2* Uu2   = reinterpret_cast<const float2*>(Uu);
    const float2* rest2 = reinterpret_cast<const float2*>(rest);
    unsigned packed = 0;
    int base = w * 5;
    #pragma unroll
    for (int k = 0; k < 5; k++) {
        int vi = base + k;
        if (vi < N_VERTS) {
            float2 u = __ldg(&Uu2[vi]);
            float2 r = __ldg(&rest2[vi]);
            float2 c = make_float2(u.x + r.x, u.y + r.y);
            g_coords[vi] = c;
            int qx = min(7, max(0, (int)(c.x * 8.0f)));
            int qy = min(7, max(0, (int)(c.y * 8.0f)));
            packed |= (unsigned)(qx | (qy << 3)) << (6 * k);
        }
    }
    g_qtab[w] = packed;
    if (w == 0) *out = 0.0f;
}

// ---------------------------------------------------------------- helpers
// 6-bit cell code for vertex v from the smem table.
__device__ __forceinline__ unsigned qcode(const unsigned* __restrict__ s, int v) {
    unsigned w = (unsigned)v / 5u;
    unsigned r = (unsigned)v - w * 5u;
    return (s[w] >> (r * 6u)) & 63u;
}

// Conservative point-segment filter in integer cell space (offsets cancel).
__device__ __forceinline__ bool cell_filter(unsigned cp, unsigned ca, unsigned cb) {
    int px = cp & 7, py = (int)(cp >> 3);
    int ax = ca & 7, ay = (int)(ca >> 3);
    int bx = cb & 7, by = (int)(cb >> 3);
    int abx = bx - ax, aby = by - ay;
    int apx = px - ax, apy = py - ay;
    int den_i = abx * abx + aby * aby;
    int num_i = apx * abx + apy * aby;
    float t = __saturatef(__fdividef((float)num_i, fmaxf((float)den_i, EPSF)));
    float dx = (float)apx - t * (float)abx;
    float dy = (float)apy - t * (float)aby;
    return (dx * dx + dy * dy) < R2CELL;
}

// ---------------------------------------------------------------- fused kernel
extern __shared__ unsigned s_qtab[];     // NWPAD words (~205 KB)

__global__ void __launch_bounds__(1024, 1)
barrier_energy_fused(const int4* __restrict__ pv,
                     const int4* __restrict__ pe0,
                     const int4* __restrict__ pe1,
                     float* __restrict__ out) {
    // Stage quantized table via 128-bit loads (L2-hot after first CTA).
    {
        const int4* src = reinterpret_cast<const int4*>(g_qtab);
        int4*       dst = reinterpret_cast<int4*>(s_qtab);
        for (int i = threadIdx.x; i < NWPAD / 4; i += blockDim.x)
            dst[i] = __ldg(&src[i]);
    }
    __syncthreads();

    float acc = 0.0f;
    const int nquads = N_PAIRS / 4;
    const int stride = gridDim.x * blockDim.x;

    for (int q = blockIdx.x * blockDim.x + threadIdx.x; q < nquads; q += stride) {
        // Streaming (evict-first) index loads: protect coords' L2 residency.
        int4 v  = __ldcs(&pv[q]);
        int4 e0 = __ldcs(&pe0[q]);
        int4 e1 = __ldcs(&pe1[q]);

        const int iv[4] = { v.x,  v.y,  v.z,  v.w  };
        const int ia[4] = { e0.x, e0.y, e0.z, e0.w };
        const int ib[4] = { e1.x, e1.y, e1.z, e1.w };

        // Phase 1: batched filters (12 independent LDS issue together).
        unsigned mask = 0;
        #pragma unroll
        for (int k = 0; k < 4; k++) {
            unsigned cp = qcode(s_qtab, iv[k]);
            unsigned ca = qcode(s_qtab, ia[k]);
            unsigned cb = qcode(s_qtab, ib[k]);
            if (cell_filter(cp, ca, cb)) mask |= (1u << k);
        }

        // Phase 2: batched predicated exact gathers (load-only if-bodies).
        float2 P[4], A[4], B[4];
        #pragma unroll
        for (int k = 0; k < 4; k++) {
            P[k] = make_float2(0.0f, 0.0f);
            A[k] = make_float2(0.0f, 0.0f);
            B[k] = make_float2(0.0f, 0.0f);
            if (mask & (1u << k)) {
                P[k] = __ldg(&g_coords[iv[k]]);
                A[k] = __ldg(&g_coords[ia[k]]);
                B[k] = __ldg(&g_coords[ib[k]]);
            }
        }

        // Phase 3: branchless exact barrier, gated by (pass && d2 < dhat2).
        #pragma unroll
        for (int k = 0; k < 4; k++) {
            float abx = B[k].x - A[k].x, aby = B[k].y - A[k].y;
            float apx = P[k].x - A[k].x, apy = P[k].y - A[k].y;
            float denom = abx * abx + aby * aby;
            float t = __saturatef((apx * abx + apy * aby) / fmaxf(denom, EPSF));
            float dx = apx - t * abx, dy = apy - t * aby;
            float d2 = dx * dx + dy * dy;
            float d2s = fmaxf(d2, EPSF);
            float g = d2s - DHAT2;
            float term = -(g * g) * __logf(d2s * (1.0f / DHAT2));
            bool valid = (mask & (1u << k)) && (d2 < DHAT2);
            acc += valid ? term : 0.0f;
        }
    }

    // Block reduction; reuse head of s_qtab as scratch after sync.
    #pragma unroll
    for (int off = 16; off > 0; off >>= 1)
        acc += __shfl_down_sync(0xFFFFFFFFu, acc, off);

    __syncthreads();
    float* warp_sums = reinterpret_cast<float*>(s_qtab);
    int lane = threadIdx.x & 31;
    int wid  = threadIdx.x >> 5;
    if (lane == 0) warp_sums[wid] = acc;
    __syncthreads();

    if (wid == 0) {
        int nw = blockDim.x >> 5;   // 32
        float s = (lane < nw) ? warp_sums[lane] : 0.0f;
        #pragma unroll
        for (int off = 16; off > 0; off >>= 1)
            s += __shfl_down_sync(0xFFFFFFFFu, s, off);
        if (lane == 0) atomicAdd(out, s);
    }
}

// ---------------------------------------------------------------- launch
extern "C" void kernel_launch(void* const* d_in, const int* in_sizes, int n_in,
                              void* d_out, int out_size) {
    const float* Uu   = (const float*)d_in[0];
    const float* rest = (const float*)d_in[1];
    const int*   pv   = (const int*)d_in[2];
    const int*   pe0  = (const int*)d_in[3];
    const int*   pe1  = (const int*)d_in[4];
    float* out = (float*)d_out;

    setup_kernel<<<(NWPAD + 255) / 256, 256>>>(Uu, rest, out);

    const size_t smem_bytes = (size_t)NWPAD * sizeof(unsigned);   // ~205 KB
    cudaFuncSetAttribute(barrier_energy_fused,
                         cudaFuncAttributeMaxDynamicSharedMemorySize,
                         (int)smem_bytes);

    int nsm = 148;
    cudaDeviceGetAttribute(&nsm, cudaDevAttrMultiProcessorCount, 0);

    barrier_energy_fused<<<nsm, 1024, smem_bytes>>>(
        (const int4*)pv, (const int4*)pe0, (const int4*)pe1, out);
}

// round 6
// speedup vs baseline: 1.0332x; 1.0332x over previous
#include <cuda_runtime.h>
#include <cuda_bf16.h>

#define N_VERTS 262144
#define N_PAIRS 8388608
#define NW      52429        // ceil(N_VERTS/5) packed words, 6 bits/vertex
#define NWPAD   52432        // padded to /4 for int4 staging
#define DHAT2   0.0025f
#define EPSF    1e-12f
// Conservative threshold in cell^2 units: true bound 3.76 (covers |u|<=5.5e-3);
// use 61/16 = 3.8125. Integer tests: 16*d2cell < 61 ; middle: 16*cross^2 < 61*den.

__device__ float2   g_coords[N_VERTS];   // 2 MB, L2-resident
__device__ unsigned g_qtab[NWPAD];       // 6-bit quantized coords, 5/word

// ---------------------------------------------------------------- setup
__global__ void setup_kernel(const float* __restrict__ Uu,
                             const float* __restrict__ rest,
                             float* __restrict__ out) {
    int w = blockIdx.x * blockDim.x + threadIdx.x;
    if (w >= NWPAD) return;
    const float2* Uu2   = reinterpret_cast<const float2*>(Uu);
    const float2* rest2 = reinterpret_cast<const float2*>(rest);
    unsigned packed = 0;
    int base = w * 5;
    #pragma unroll
    for (int k = 0; k < 5; k++) {
        int vi = base + k;
        if (vi < N_VERTS) {
            float2 u = __ldg(&Uu2[vi]);
            float2 r = __ldg(&rest2[vi]);
            float2 c = make_float2(u.x + r.x, u.y + r.y);
            g_coords[vi] = c;
            int qx = min(7, max(0, (int)(c.x * 8.0f)));
            int qy = min(7, max(0, (int)(c.y * 8.0f)));
            packed |= (unsigned)(qx | (qy << 3)) << (6 * k);
        }
    }
    g_qtab[w] = packed;
    if (w == 0) *out = 0.0f;
}

// ---------------------------------------------------------------- helpers
__device__ __forceinline__ unsigned qcode(const unsigned* __restrict__ s, int v) {
    unsigned w = (unsigned)v / 5u;
    unsigned r = (unsigned)v - w * 5u;
    return (s[w] >> (r * 6u)) & 63u;
}

// Integer-only conservative point-segment filter in cell space.
// d2(cells): num<=0 -> |ap|^2 ; num>=den -> |bp|^2 ; else cross^2/den
// (Lagrange: ap2*den - num^2 = cross^2). Pass iff d2 < 61/16 cells^2.
__device__ __forceinline__ bool cell_filter(unsigned cp, unsigned ca, unsigned cb) {
    int px = cp & 7, py = (int)(cp >> 3);
    int ax = ca & 7, ay = (int)(ca >> 3);
    int bx = cb & 7, by = (int)(cb >> 3);
    int abx = bx - ax, aby = by - ay;
    int apx = px - ax, apy = py - ay;
    int den = abx * abx + aby * aby;
    int num = apx * abx + apy * aby;
    int ap2 = apx * apx + apy * apy;
    int bp2 = ap2 - 2 * num + den;
    int cr  = apx * aby - apy * abx;        // cross product
    bool pass_a = (16 * ap2) < 61;
    bool pass_b = (16 * bp2) < 61;
    bool pass_m = (16 * cr * cr) < (61 * den);   // FIXED: was 64*cr*cr (4x too tight)
    return (num <= 0) ? pass_a : (num >= den) ? pass_b : pass_m;
}

// ---------------------------------------------------------------- fused kernel
extern __shared__ unsigned s_qtab[];     // NWPAD words (~205 KB)

#define BLKT 896

__global__ void __launch_bounds__(BLKT, 1)
barrier_energy_fused(const int4* __restrict__ pv,
                     const int4* __restrict__ pe0,
                     const int4* __restrict__ pe1,
                     float* __restrict__ out) {
    // Stage quantized table via 128-bit loads.
    {
        const int4* src = reinterpret_cast<const int4*>(g_qtab);
        int4*       dst = reinterpret_cast<int4*>(s_qtab);
        for (int i = threadIdx.x; i < NWPAD / 4; i += blockDim.x)
            dst[i] = __ldg(&src[i]);
    }
    __syncthreads();

    float acc = 0.0f;
    const int nquads = N_PAIRS / 4;
    const int stride = gridDim.x * blockDim.x;

    int q = blockIdx.x * blockDim.x + threadIdx.x;
    if (q < nquads) {
        // prime the pipeline
        int4 v  = __ldcs(&pv[q]);
        int4 e0 = __ldcs(&pe0[q]);
        int4 e1 = __ldcs(&pe1[q]);

        while (true) {
            // ---- prefetch next iteration's indices (hide DRAM latency) ----
            int qn = q + stride;
            bool has_next = qn < nquads;
            int4 vn, e0n, e1n;
            if (has_next) {
                vn  = __ldcs(&pv[qn]);
                e0n = __ldcs(&pe0[qn]);
                e1n = __ldcs(&pe1[qn]);
            }

            const int iv[4] = { v.x,  v.y,  v.z,  v.w  };
            const int ia[4] = { e0.x, e0.y, e0.z, e0.w };
            const int ib[4] = { e1.x, e1.y, e1.z, e1.w };

            // Phase 1: batched integer filters (12 independent LDS).
            unsigned mask = 0;
            #pragma unroll
            for (int k = 0; k < 4; k++) {
                unsigned cp = qcode(s_qtab, iv[k]);
                unsigned ca = qcode(s_qtab, ia[k]);
                unsigned cb = qcode(s_qtab, ib[k]);
                if (cell_filter(cp, ca, cb)) mask |= (1u << k);
            }

            // Phase 2: batched predicated exact gathers.
            float2 P[4], A[4], B[4];
            #pragma unroll
            for (int k = 0; k < 4; k++) {
                P[k] = make_float2(0.0f, 0.0f);
                A[k] = make_float2(0.0f, 0.0f);
                B[k] = make_float2(0.0f, 0.0f);
                if (mask & (1u << k)) {
                    P[k] = __ldg(&g_coords[iv[k]]);
                    A[k] = __ldg(&g_coords[ia[k]]);
                    B[k] = __ldg(&g_coords[ib[k]]);
                }
            }

            // Phase 3: branchless exact barrier.
            #pragma unroll
            for (int k = 0; k < 4; k++) {
                float abx = B[k].x - A[k].x, aby = B[k].y - A[k].y;
                float apx = P[k].x - A[k].x, apy = P[k].y - A[k].y;
                float denom = abx * abx + aby * aby;
                float t = __saturatef(__fdividef(apx * abx + apy * aby,
                                                 fmaxf(denom, EPSF)));
                float dx = apx - t * abx, dy = apy - t * aby;
                float d2 = dx * dx + dy * dy;
                float d2s = fmaxf(d2, EPSF);
                float g = d2s - DHAT2;
                float term = -(g * g) * __logf(d2s * (1.0f / DHAT2));
                bool valid = (mask & (1u << k)) && (d2 < DHAT2);
                acc += valid ? term : 0.0f;
            }

            if (!has_next) break;
            v = vn; e0 = e0n; e1 = e1n; q = qn;
        }
    }

    // Block reduction; reuse head of s_qtab as scratch after sync.
    #pragma unroll
    for (int off = 16; off > 0; off >>= 1)
        acc += __shfl_down_sync(0xFFFFFFFFu, acc, off);

    __syncthreads();
    float* warp_sums = reinterpret_cast<float*>(s_qtab);
    int lane = threadIdx.x & 31;
    int wid  = threadIdx.x >> 5;
    if (lane == 0) warp_sums[wid] = acc;
    __syncthreads();

    if (wid == 0) {
        int nw = blockDim.x >> 5;   // 28
        float s = (lane < nw) ? warp_sums[lane] : 0.0f;
        #pragma unroll
        for (int off = 16; off > 0; off >>= 1)
            s += __shfl_down_sync(0xFFFFFFFFu, s, off);
        if (lane == 0) atomicAdd(out, s);
    }
}

// ---------------------------------------------------------------- launch
extern "C" void kernel_launch(void* const* d_in, const int* in_sizes, int n_in,
                              void* d_out, int out_size) {
    const float* Uu   = (const float*)d_in[0];
    const float* rest = (const float*)d_in[1];
    const int*   pv   = (const int*)d_in[2];
    const int*   pe0  = (const int*)d_in[3];
    const int*   pe1  = (const int*)d_in[4];
    float* out = (float*)d_out;

    setup_kernel<<<(NWPAD + 255) / 256, 256>>>(Uu, rest, out);

    const size_t smem_bytes = (size_t)NWPAD * sizeof(unsigned);   // ~205 KB
    cudaFuncSetAttribute(barrier_energy_fused,
                         cudaFuncAttributeMaxDynamicSharedMemorySize,
                         (int)smem_bytes);

    int nsm = 148;
    cudaDeviceGetAttribute(&nsm, cudaDevAttrMultiProcessorCount, 0);

    barrier_energy_fused<<<nsm, BLKT, smem_bytes>>>(
        (const int4*)pv, (const int4*)pe0, (const int4*)pe1, out);
}

// round 7
// speedup vs baseline: 1.0541x; 1.0203x over previous
#include <cuda_runtime.h>
#include <cuda_bf16.h>

#define N_VERTS 262144
#define N_PAIRS 8388608
#define NW      52429        // ceil(N_VERTS/5) packed words, 6 bits/vertex
#define NWPAD   52432        // padded to /4 for int4 staging
#define DHAT2   0.0025f
#define EPSF    1e-12f
// Conservative threshold in cell^2 units (cell = 0.125): true bound 3.76;
// use 61/16 = 3.8125. Tests: 16*ap2<61, 16*bp2<61, 16*cr^2<61*den.

__device__ float2   g_coords[N_VERTS];   // 2 MB, L2-resident
__device__ unsigned g_qtab[NWPAD];       // 6-bit quantized coords, 5/word

// ---------------------------------------------------------------- setup
__global__ void setup_kernel(const float* __restrict__ Uu,
                             const float* __restrict__ rest,
                             float* __restrict__ out) {
    int w = blockIdx.x * blockDim.x + threadIdx.x;
    if (w >= NWPAD) return;
    const float2* Uu2   = reinterpret_cast<const float2*>(Uu);
    const float2* rest2 = reinterpret_cast<const float2*>(rest);
    unsigned packed = 0;
    int base = w * 5;
    #pragma unroll
    for (int k = 0; k < 5; k++) {
        int vi = base + k;
        if (vi < N_VERTS) {
            float2 u = __ldg(&Uu2[vi]);
            float2 r = __ldg(&rest2[vi]);
            float2 c = make_float2(u.x + r.x, u.y + r.y);
            g_coords[vi] = c;
            int qx = min(7, max(0, (int)(c.x * 8.0f)));
            int qy = min(7, max(0, (int)(c.y * 8.0f)));
            packed |= (unsigned)(qx | (qy << 3)) << (6 * k);
        }
    }
    g_qtab[w] = packed;
    if (w == 0) *out = 0.0f;
}

// ---------------------------------------------------------------- helpers
__device__ __forceinline__ unsigned qcode(const unsigned* __restrict__ s, int v) {
    unsigned w = (unsigned)v / 5u;
    unsigned r = (unsigned)v - w * 5u;
    return (s[w] >> (r * 6u)) & 63u;
}

// Integer-only conservative point-segment filter in cell space.
__device__ __forceinline__ bool cell_filter(unsigned cp, unsigned ca, unsigned cb) {
    int px = cp & 7, py = (int)(cp >> 3);
    int ax = ca & 7, ay = (int)(ca >> 3);
    int bx = cb & 7, by = (int)(cb >> 3);
    int abx = bx - ax, aby = by - ay;
    int apx = px - ax, apy = py - ay;
    int den = abx * abx + aby * aby;
    int num = apx * abx + apy * aby;
    int ap2 = apx * apx + apy * apy;
    int bp2 = ap2 - 2 * num + den;
    int cr  = apx * aby - apy * abx;
    bool pass_a = (16 * ap2) < 61;
    bool pass_b = (16 * bp2) < 61;
    bool pass_m = (16 * cr * cr) < (61 * den);
    return (num <= 0) ? pass_a : (num >= den) ? pass_b : pass_m;
}

// Filter 4 pairs + issue predicated gathers. Returns pass mask.
__device__ __forceinline__ unsigned filter_and_gather(
        const unsigned* __restrict__ s,
        int4 v, int4 e0, int4 e1,
        float2* __restrict__ P, float2* __restrict__ A, float2* __restrict__ B) {
    const int iv[4] = { v.x,  v.y,  v.z,  v.w  };
    const int ia[4] = { e0.x, e0.y, e0.z, e0.w };
    const int ib[4] = { e1.x, e1.y, e1.z, e1.w };
    unsigned mask = 0;
    #pragma unroll
    for (int k = 0; k < 4; k++) {
        unsigned cp = qcode(s, iv[k]);
        unsigned ca = qcode(s, ia[k]);
        unsigned cb = qcode(s, ib[k]);
        if (cell_filter(cp, ca, cb)) mask |= (1u << k);
    }
    #pragma unroll
    for (int k = 0; k < 4; k++) {
        P[k] = make_float2(0.0f, 0.0f);
        A[k] = make_float2(0.0f, 0.0f);
        B[k] = make_float2(0.0f, 0.0f);
        if (mask & (1u << k)) {
            P[k] = __ldg(&g_coords[iv[k]]);
            A[k] = __ldg(&g_coords[ia[k]]);
            B[k] = __ldg(&g_coords[ib[k]]);
        }
    }
    return mask;
}

// Branchless exact barrier for 4 gathered pairs.
__device__ __forceinline__ float compute4(unsigned mask,
        const float2* __restrict__ P, const float2* __restrict__ A,
        const float2* __restrict__ B) {
    float acc = 0.0f;
    #pragma unroll
    for (int k = 0; k < 4; k++) {
        float abx = B[k].x - A[k].x, aby = B[k].y - A[k].y;
        float apx = P[k].x - A[k].x, apy = P[k].y - A[k].y;
        float denom = abx * abx + aby * aby;
        float t = __saturatef(__fdividef(apx * abx + apy * aby,
                                         fmaxf(denom, EPSF)));
        float dx = apx - t * abx, dy = apy - t * aby;
        float d2 = dx * dx + dy * dy;
        float d2s = fmaxf(d2, EPSF);
        float g = d2s - DHAT2;
        float term = -(g * g) * __logf(d2s * (1.0f / DHAT2));
        bool valid = (mask & (1u << k)) && (d2 < DHAT2);
        acc += valid ? term : 0.0f;
    }
    return acc;
}

// ---------------------------------------------------------------- fused kernel
extern __shared__ unsigned s_qtab[];     // NWPAD words (~205 KB)

#define BLKT 768

__global__ void __launch_bounds__(BLKT, 1)
barrier_energy_fused(const int4* __restrict__ pv,
                     const int4* __restrict__ pe0,
                     const int4* __restrict__ pe1,
                     float* __restrict__ out) {
    // Stage quantized table via 128-bit loads.
    {
        const int4* src = reinterpret_cast<const int4*>(g_qtab);
        int4*       dst = reinterpret_cast<int4*>(s_qtab);
        for (int i = threadIdx.x; i < NWPAD / 4; i += blockDim.x)
            dst[i] = __ldg(&src[i]);
    }
    __syncthreads();

    float acc = 0.0f;
    const int nquads = N_PAIRS / 4;
    const int stride = gridDim.x * blockDim.x;

    // ---- two-stage rotation pipeline ----
    // Stage A: gathers in flight (maskA, PA/AA/BA) — consumed by compute.
    // Stage B: indices loaded (vB/e0B/e1B)       — filtered+gathered next.
    int qA = blockIdx.x * blockDim.x + threadIdx.x;
    int qB = qA + stride;
    bool okA = qA < nquads;
    bool okB = qB < nquads;

    unsigned maskA = 0;
    float2 PA[4], AA[4], BA[4];
    int4 vB, e0B, e1B;

    if (okA) {
        int4 v  = __ldcs(&pv[qA]);
        int4 e0 = __ldcs(&pe0[qA]);
        int4 e1 = __ldcs(&pe1[qA]);
        maskA = filter_and_gather(s_qtab, v, e0, e1, PA, AA, BA);
    }
    if (okB) {
        vB  = __ldcs(&pv[qB]);
        e0B = __ldcs(&pe0[qB]);
        e1B = __ldcs(&pe1[qB]);
    }

    while (okA) {
        // 1) issue index loads for iteration C (two ahead)
        int qC = qB + stride;
        bool okC = qC < nquads;
        int4 vC, e0C, e1C;
        if (okC) {
            vC  = __ldcs(&pv[qC]);
            e0C = __ldcs(&pe0[qC]);
            e1C = __ldcs(&pe1[qC]);
        }

        // 2) filter B and issue its gathers (LDS + LDG, results needed next iter)
        unsigned maskB = 0;
        float2 PB[4], AB[4], BB[4];
        if (okB) maskB = filter_and_gather(s_qtab, vB, e0B, e1B, PB, AB, BB);

        // 3) compute A (its gathers were issued a full iteration ago)
        acc += compute4(maskA, PA, AA, BA);

        // 4) rotate
        maskA = maskB;
        #pragma unroll
        for (int k = 0; k < 4; k++) { PA[k] = PB[k]; AA[k] = AB[k]; BA[k] = BB[k]; }
        okA = okB;
        okB = okC;
        vB = vC; e0B = e0C; e1B = e1C;
        qB = qC;
    }

    // Block reduction; reuse head of s_qtab as scratch after sync.
    #pragma unroll
    for (int off = 16; off > 0; off >>= 1)
        acc += __shfl_down_sync(0xFFFFFFFFu, acc, off);

    __syncthreads();
    float* warp_sums = reinterpret_cast<float*>(s_qtab);
    int lane = threadIdx.x & 31;
    int wid  = threadIdx.x >> 5;
    if (lane == 0) warp_sums[wid] = acc;
    __syncthreads();

    if (wid == 0) {
        int nw = blockDim.x >> 5;   // 24
        float s = (lane < nw) ? warp_sums[lane] : 0.0f;
        #pragma unroll
        for (int off = 16; off > 0; off >>= 1)
            s += __shfl_down_sync(0xFFFFFFFFu, s, off);
        if (lane == 0) atomicAdd(out, s);
    }
}

// ---------------------------------------------------------------- launch
extern "C" void kernel_launch(void* const* d_in, const int* in_sizes, int n_in,
                              void* d_out, int out_size) {
    const float* Uu   = (const float*)d_in[0];
    const float* rest = (const float*)d_in[1];
    const int*   pv   = (const int*)d_in[2];
    const int*   pe0  = (const int*)d_in[3];
    const int*   pe1  = (const int*)d_in[4];
    float* out = (float*)d_out;

    setup_kernel<<<(NWPAD + 255) / 256, 256>>>(Uu, rest, out);

    const size_t smem_bytes = (size_t)NWPAD * sizeof(unsigned);   // ~205 KB
    cudaFuncSetAttribute(barrier_energy_fused,
                         cudaFuncAttributeMaxDynamicSharedMemorySize,
                         (int)smem_bytes);

    int nsm = 148;
    cudaDeviceGetAttribute(&nsm, cudaDevAttrMultiProcessorCount, 0);

    barrier_energy_fused<<<nsm, BLKT, smem_bytes>>>(
        (const int4*)pv, (const int4*)pe0, (const int4*)pe1, out);
}